// round 5
// baseline (speedup 1.0000x reference)
#include <cuda_runtime.h>
#include <cuda_fp16.h>

// TM-CFAR: out = rd / trimmed_mean( sorted( 9x15 window minus 3x3 guard )[31:94] )
// 8 x 512 x 512 float32 input, zero padding at borders.

#define IMG_W 512
#define IMG_H 512
#define BATCH 8

#define BLK_PX_X 64   // pixels in x per block (32 threads x 2 px each)
#define BLK_PX_Y 4    // pixel rows per block
#define TILE_W   79   // BLK_PX_X + 7 (left halo) + 8 (right halo incl. pixel1 reach)
#define TILE_H   12   // BLK_PX_Y + 8
#define TSTRIDE  80   // padded row stride in halves

#define N_SORT 128    // 126 refs + 2 pads
#define LOWER 31
#define UPPER 94      // sum ranks [31,94) = 63 values

__global__ __launch_bounds__(128)
void tmcfar_kernel(const float* __restrict__ in, float* __restrict__ out)
{
    // Copy A: natural layout.  Copy B: shifted left by one half, so a half2
    // starting at an ODD logical index q is a 4B-aligned load from B[q-1].
    __shared__ __align__(16) unsigned short sA[TILE_H][TSTRIDE];
    __shared__ __align__(16) unsigned short sB[TILE_H][TSTRIDE];

    const int b   = blockIdx.z;
    const int bx0 = blockIdx.x * BLK_PX_X;
    const int by0 = blockIdx.y * BLK_PX_Y;
    const int tid = threadIdx.y * 32 + threadIdx.x;

    const float* img = in + (size_t)b * IMG_W * IMG_H;

    // ---- cooperative tile load (f32 -> f16, zero-pad out of range) ----
    #pragma unroll
    for (int idx = tid; idx < TILE_H * TILE_W; idx += 128) {
        int r  = idx / TILE_W;
        int c  = idx - r * TILE_W;
        int gy = by0 - 4 + r;
        int gx = bx0 - 7 + c;
        float vv = 0.0f;
        if (gy >= 0 && gy < IMG_H && gx >= 0 && gx < IMG_W)
            vv = __ldg(&img[gy * IMG_W + gx]);
        unsigned short h = __half_as_ushort(__float2half_rn(vv));
        sA[r][c] = h;
        if (c >= 1) sB[r][c - 1] = h;
    }
    __syncthreads();

    const int tx = threadIdx.x;
    const int ty = threadIdx.y;
    const int lx = 7 + 2 * tx;   // local column of pixel0 (always odd)
    const int lr = 4 + ty;       // local row of pixel row
    const int x0 = bx0 + 2 * tx;
    const int y  = by0 + ty;

    // ---- gather 126 reference half2 cells (lane0 = pixel x0, lane1 = x0+1) ----
    __half2 v[N_SORT];
    {
        int idx = 0;
        #pragma unroll
        for (int dy = -4; dy <= 4; dy++) {
            const unsigned short* rowA = sA[lr + dy];
            const unsigned short* rowB = sB[lr + dy];
            #pragma unroll
            for (int dx = -7; dx <= 7; dx++) {
                if (dy >= -1 && dy <= 1 && dx >= -1 && dx <= 1) continue; // guard
                const int q = lx + dx;                 // logical start index
                // parity of q == parity of (7+dx): compile-time per dx
                if (((7 + dx) & 1) == 0) {
                    v[idx++] = *reinterpret_cast<const __half2*>(rowA + q);
                } else {
                    v[idx++] = *reinterpret_cast<const __half2*>(rowB + (q - 1));
                }
            }
        }
        // pad to 128 with +INF (sinks to ranks 126,127; never in [31,94))
        const __half2 inf2 = __half2half2(__ushort_as_half((unsigned short)0x7C00));
        v[126] = inf2;
        v[127] = inf2;
    }

    // ---- Batcher odd-even mergesort, n=128, fully unrolled (1471 CEs) ----
    #define CE(A, B) { __half2 _mn = __hmin2(A, B); __half2 _mx = __hmax2(A, B); (A) = _mn; (B) = _mx; }
    #pragma unroll
    for (int p = 1; p < N_SORT; p <<= 1) {
        #pragma unroll
        for (int k = p; k >= 1; k >>= 1) {
            #pragma unroll
            for (int j = k % p; j + k < N_SORT; j += 2 * k) {
                #pragma unroll
                for (int i = 0; i < k; i++) {
                    if (i + j + k < N_SORT) {
                        if ((i + j) / (2 * p) == (i + j + k) / (2 * p)) {
                            CE(v[i + j], v[i + j + k]);
                        }
                    }
                }
            }
        }
    }
    #undef CE

    // ---- trimmed sum (fp32 accumulation) ----
    float s0 = 0.0f, s1 = 0.0f;
    #pragma unroll
    for (int i = LOWER; i < UPPER; i++) {
        float2 f = __half22float2(v[i]);
        s0 += f.x;
        s1 += f.y;
    }

    // ---- divide original fp32 values by trimmed mean, vectorized store ----
    const float r0 = __ldg(&img[y * IMG_W + x0]);
    const float r1 = __ldg(&img[y * IMG_W + x0 + 1]);
    float2 o;
    o.x = r0 * __fdividef(63.0f, s0);
    o.y = r1 * __fdividef(63.0f, s1);
    *reinterpret_cast<float2*>(out + (size_t)b * IMG_W * IMG_H + y * IMG_W + x0) = o;
}

extern "C" void kernel_launch(void* const* d_in, const int* in_sizes, int n_in,
                              void* d_out, int out_size)
{
    const float* rd = (const float*)d_in[0];
    float* out = (float*)d_out;
    dim3 block(32, 4, 1);
    dim3 grid(IMG_W / BLK_PX_X, IMG_H / BLK_PX_Y, BATCH);
    tmcfar_kernel<<<grid, block>>>(rd, out);
}

// round 9
// speedup vs baseline: 1.0084x; 1.0084x over previous
#include <cuda_runtime.h>
#include <cuda_fp16.h>

// TM-CFAR: out = rd / trimmed_mean( sorted( 9x15 window minus 3x3 guard )[31:94] )
// 8 x 512 x 512 float32 input, zero padding at borders.

#define IMG_W 512
#define IMG_H 512
#define BATCH 8

#define BLK_PX_X 64   // pixels in x per block (32 threads x 2 px each)
#define BLK_PX_Y 4    // pixel rows per block
#define TILE_W   79   // BLK_PX_X + 7 (left halo) + 8 (right halo incl. pixel1 reach)
#define TILE_H   12   // BLK_PX_Y + 8
#define TSTRIDE  80   // padded row stride in halves

#define N_SORT 128    // 126 refs + 2 pads
#define LOWER 31
#define UPPER 94      // sum ranks [31,94) = 63 values

// minBlocksPerMultiprocessor=1: allow ptxas the full 255-register budget so the
// 128 x half2 sort array stays register-resident (R5: default heuristic chose
// 110 regs and spilled the array to local -> L1 77% busy, 1.4ms).
__global__ __launch_bounds__(128, 1)
void tmcfar_kernel(const float* __restrict__ in, float* __restrict__ out)
{
    // Copy A: natural layout.  Copy B: shifted left by one half, so a half2
    // starting at an ODD logical index q is a 4B-aligned load from B[q-1].
    __shared__ __align__(16) unsigned short sA[TILE_H][TSTRIDE];
    __shared__ __align__(16) unsigned short sB[TILE_H][TSTRIDE];

    const int b   = blockIdx.z;
    const int bx0 = blockIdx.x * BLK_PX_X;
    const int by0 = blockIdx.y * BLK_PX_Y;
    const int tid = threadIdx.y * 32 + threadIdx.x;

    const float* img = in + (size_t)b * IMG_W * IMG_H;

    // ---- cooperative tile load (f32 -> f16, zero-pad out of range) ----
    #pragma unroll
    for (int idx = tid; idx < TILE_H * TILE_W; idx += 128) {
        int r  = idx / TILE_W;
        int c  = idx - r * TILE_W;
        int gy = by0 - 4 + r;
        int gx = bx0 - 7 + c;
        float vv = 0.0f;
        if (gy >= 0 && gy < IMG_H && gx >= 0 && gx < IMG_W)
            vv = __ldg(&img[gy * IMG_W + gx]);
        unsigned short h = __half_as_ushort(__float2half_rn(vv));
        sA[r][c] = h;
        if (c >= 1) sB[r][c - 1] = h;
    }
    __syncthreads();

    const int tx = threadIdx.x;
    const int ty = threadIdx.y;
    const int lx = 7 + 2 * tx;   // local column of pixel0 (always odd)
    const int lr = 4 + ty;       // local row of pixel row
    const int x0 = bx0 + 2 * tx;
    const int y  = by0 + ty;

    // ---- gather 126 reference half2 cells (lane0 = pixel x0, lane1 = x0+1) ----
    __half2 v[N_SORT];
    {
        int idx = 0;
        #pragma unroll
        for (int dy = -4; dy <= 4; dy++) {
            const unsigned short* rowA = sA[lr + dy];
            const unsigned short* rowB = sB[lr + dy];
            #pragma unroll
            for (int dx = -7; dx <= 7; dx++) {
                if (dy >= -1 && dy <= 1 && dx >= -1 && dx <= 1) continue; // guard
                const int q = lx + dx;                 // logical start index
                // parity of q == parity of (7+dx): compile-time per dx
                if (((7 + dx) & 1) == 0) {
                    v[idx++] = *reinterpret_cast<const __half2*>(rowA + q);
                } else {
                    v[idx++] = *reinterpret_cast<const __half2*>(rowB + (q - 1));
                }
            }
        }
        // pad to 128 with +INF (sinks to ranks 126,127; never in [31,94))
        const __half2 inf2 = __half2half2(__ushort_as_half((unsigned short)0x7C00));
        v[126] = inf2;
        v[127] = inf2;
    }

    // ---- Batcher odd-even mergesort, n=128, fully unrolled (1471 CEs) ----
    #define CE(A, B) { __half2 _mn = __hmin2(A, B); __half2 _mx = __hmax2(A, B); (A) = _mn; (B) = _mx; }
    #pragma unroll
    for (int p = 1; p < N_SORT; p <<= 1) {
        #pragma unroll
        for (int k = p; k >= 1; k >>= 1) {
            #pragma unroll
            for (int j = k % p; j + k < N_SORT; j += 2 * k) {
                #pragma unroll
                for (int i = 0; i < k; i++) {
                    if (i + j + k < N_SORT) {
                        if ((i + j) / (2 * p) == (i + j + k) / (2 * p)) {
                            CE(v[i + j], v[i + j + k]);
                        }
                    }
                }
            }
        }
    }
    #undef CE

    // ---- trimmed sum (fp32 accumulation) ----
    float s0 = 0.0f, s1 = 0.0f;
    #pragma unroll
    for (int i = LOWER; i < UPPER; i++) {
        float2 f = __half22float2(v[i]);
        s0 += f.x;
        s1 += f.y;
    }

    // ---- divide original fp32 values by trimmed mean, vectorized store ----
    const float r0 = __ldg(&img[y * IMG_W + x0]);
    const float r1 = __ldg(&img[y * IMG_W + x0 + 1]);
    float2 o;
    o.x = r0 * __fdividef(63.0f, s0);
    o.y = r1 * __fdividef(63.0f, s1);
    *reinterpret_cast<float2*>(out + (size_t)b * IMG_W * IMG_H + y * IMG_W + x0) = o;
}

extern "C" void kernel_launch(void* const* d_in, const int* in_sizes, int n_in,
                              void* d_out, int out_size)
{
    const float* rd = (const float*)d_in[0];
    float* out = (float*)d_out;
    dim3 block(32, 4, 1);
    dim3 grid(IMG_W / BLK_PX_X, IMG_H / BLK_PX_Y, BATCH);
    tmcfar_kernel<<<grid, block>>>(rd, out);
}

// round 12
// speedup vs baseline: 6.7433x; 6.6874x over previous
#include <cuda_runtime.h>
#include <cuda_fp16.h>
#include <utility>

// TM-CFAR: out = rd / trimmed_mean( sorted( 9x15 window minus 3x3 guard )[31:94] )
// 8 x 512 x 512 float32 input, zero padding at borders.

#define IMG_W 512
#define IMG_H 512
#define BATCH 8

#define BLK_PX_X 64   // pixels in x per block (32 threads x 2 px each)
#define BLK_PX_Y 4    // pixel rows per block
#define TILE_W   79   // BLK_PX_X + 7 (left halo) + 8 (right halo incl. pixel1 reach)
#define TILE_H   12   // BLK_PX_Y + 8
#define TSTRIDE  80   // padded row stride in halves

#define N_SORT 128    // 126 refs + 2 pads
#define LOWER 31
#define UPPER 94      // sum ranks [31,94) = 63 values

// ---------------------------------------------------------------------------
// Compile-time Batcher odd-even mergesort network for n=128 (1471 CE pairs).
// R9 diagnosis: nvcc did not fully unroll the runtime loop nest -> dynamic
// indices -> sort array demoted to local memory (L1 77%, 1.39 ms).
// R11 diagnosis: host constexpr object referenced as a RUNTIME expression in
// device code fails without --expt-relaxed-constexpr. Fix: deliver the pair
// indices as NON-TYPE TEMPLATE PARAMETERS — template arguments are evaluated
// at compile time by the front end, so NET is never touched by device codegen
// and every v[] index is a literal.
// ---------------------------------------------------------------------------
constexpr int net_count() {
    int n = 0;
    for (int p = 1; p < N_SORT; p <<= 1)
        for (int k = p; k >= 1; k >>= 1)
            for (int j = k % p; j + k < N_SORT; j += 2 * k)
                for (int i = 0; i < k; i++)
                    if ((i + j) / (2 * p) == (i + j + k) / (2 * p)) n++;
    return n;
}
constexpr int NET_N = net_count();

struct Net { unsigned char a[NET_N]; unsigned char b[NET_N]; };

constexpr Net build_net() {
    Net net{};
    int n = 0;
    for (int p = 1; p < N_SORT; p <<= 1)
        for (int k = p; k >= 1; k >>= 1)
            for (int j = k % p; j + k < N_SORT; j += 2 * k)
                for (int i = 0; i < k; i++)
                    if ((i + j) / (2 * p) == (i + j + k) / (2 * p)) {
                        net.a[n] = (unsigned char)(i + j);
                        net.b[n] = (unsigned char)(i + j + k);
                        n++;
                    }
    return net;
}
constexpr Net NET = build_net();

__device__ __forceinline__ void ce(__half2& x, __half2& y) {
    __half2 mn = __hmin2(x, y);
    __half2 mx = __hmax2(x, y);
    x = mn;
    y = mx;
}

// A and B are compile-time literals: v[A]/v[B] are constant indices.
template <int A, int B>
__device__ __forceinline__ void ce_ab(__half2* v) {
    ce(v[A], v[B]);
}

template <std::size_t... Is>
__device__ __forceinline__ void run_sort(__half2* v, std::index_sequence<Is...>) {
    // NET.a[Is] / NET.b[Is] appear ONLY as template arguments (compile-time).
    (ce_ab<(int)NET.a[Is], (int)NET.b[Is]>(v), ...);
}

__global__ __launch_bounds__(128, 1)
void tmcfar_kernel(const float* __restrict__ in, float* __restrict__ out)
{
    // Copy A: natural layout.  Copy B: shifted left by one half, so a half2
    // starting at an ODD logical index q is a 4B-aligned load from B[q-1].
    __shared__ __align__(16) unsigned short sA[TILE_H][TSTRIDE];
    __shared__ __align__(16) unsigned short sB[TILE_H][TSTRIDE];

    const int b   = blockIdx.z;
    const int bx0 = blockIdx.x * BLK_PX_X;
    const int by0 = blockIdx.y * BLK_PX_Y;
    const int tid = threadIdx.y * 32 + threadIdx.x;

    const float* img = in + (size_t)b * IMG_W * IMG_H;

    // ---- cooperative tile load (f32 -> f16, zero-pad out of range) ----
    #pragma unroll
    for (int idx = tid; idx < TILE_H * TILE_W; idx += 128) {
        int r  = idx / TILE_W;
        int c  = idx - r * TILE_W;
        int gy = by0 - 4 + r;
        int gx = bx0 - 7 + c;
        float vv = 0.0f;
        if (gy >= 0 && gy < IMG_H && gx >= 0 && gx < IMG_W)
            vv = __ldg(&img[gy * IMG_W + gx]);
        unsigned short h = __half_as_ushort(__float2half_rn(vv));
        sA[r][c] = h;
        if (c >= 1) sB[r][c - 1] = h;
    }
    __syncthreads();

    const int tx = threadIdx.x;
    const int ty = threadIdx.y;
    const int lx = 7 + 2 * tx;   // local column of pixel0 (always odd)
    const int lr = 4 + ty;       // local row of pixel row
    const int x0 = bx0 + 2 * tx;
    const int y  = by0 + ty;

    // ---- gather 126 reference half2 cells (lane0 = pixel x0, lane1 = x0+1) ----
    __half2 v[N_SORT];
    {
        int idx = 0;
        #pragma unroll
        for (int dy = -4; dy <= 4; dy++) {
            const unsigned short* rowA = sA[lr + dy];
            const unsigned short* rowB = sB[lr + dy];
            #pragma unroll
            for (int dx = -7; dx <= 7; dx++) {
                if (dy >= -1 && dy <= 1 && dx >= -1 && dx <= 1) continue; // guard
                const int q = lx + dx;                 // logical start index
                // parity of q == parity of (7+dx): compile-time per dx
                if (((7 + dx) & 1) == 0) {
                    v[idx++] = *reinterpret_cast<const __half2*>(rowA + q);
                } else {
                    v[idx++] = *reinterpret_cast<const __half2*>(rowB + (q - 1));
                }
            }
        }
        // pad to 128 with +INF (sinks to ranks 126,127; never in [31,94))
        const __half2 inf2 = __half2half2(__ushort_as_half((unsigned short)0x7C00));
        v[126] = inf2;
        v[127] = inf2;
    }

    // ---- Batcher sort as straight-line code (compile-time network) ----
    run_sort(v, std::make_index_sequence<NET_N>{});

    // ---- trimmed sum (fp32 accumulation) ----
    float s0 = 0.0f, s1 = 0.0f;
    #pragma unroll
    for (int i = LOWER; i < UPPER; i++) {
        float2 f = __half22float2(v[i]);
        s0 += f.x;
        s1 += f.y;
    }

    // ---- divide original fp32 values by trimmed mean, vectorized store ----
    const float r0 = __ldg(&img[y * IMG_W + x0]);
    const float r1 = __ldg(&img[y * IMG_W + x0 + 1]);
    float2 o;
    o.x = r0 * __fdividef(63.0f, s0);
    o.y = r1 * __fdividef(63.0f, s1);
    *reinterpret_cast<float2*>(out + (size_t)b * IMG_W * IMG_H + y * IMG_W + x0) = o;
}

extern "C" void kernel_launch(void* const* d_in, const int* in_sizes, int n_in,
                              void* d_out, int out_size)
{
    const float* rd = (const float*)d_in[0];
    float* out = (float*)d_out;
    dim3 block(32, 4, 1);
    dim3 grid(IMG_W / BLK_PX_X, IMG_H / BLK_PX_Y, BATCH);
    tmcfar_kernel<<<grid, block>>>(rd, out);
}